// round 5
// baseline (speedup 1.0000x reference)
#include <cuda_runtime.h>
#include <cstdint>
#include <cstddef>

// Problem constants (fixed by the dataset)
#define B_  32
#define N_  1024
#define D_  128
#define C_  16
// P*P = 16, Hg = 32, out image 128x128 per (b,c)

// Tiling: thread t -> (row = t>>2, q = t&3); 4 lanes share one x row (smem broadcast)
#define NT      64
#define THREADS 256

// Shared layout (floats) — x tile XOR-swizzled at 16B-chunk granularity
#define SX_OFF    0                    // [64][128] swizzled, 32KB
#define SW_OFF    (NT * D_)            // 8192: [16][128] swizzled
#define SCBM_OFF  (SW_OFF + 16 * D_)   // 10240: [16][16] mask-premultiplied
#define SMASK_OFF (SCBM_OFF + 256)     // 10496: [16]
#define SMEM_FLOATS (SMASK_OFF + 16)   // 10512
#define SMEM_BYTES  (SMEM_FLOATS * 4)  // 42048 -> >=4 CTAs/SM; 512-CTA grid fits in ONE wave

// Precomputed channel table: cb[c*16+p] = emb[c]·W[p] + bias[p]
__device__ float g_cb[C_ * 16];

__device__ __forceinline__ uint32_t smem_u32(const void* p) {
    return (uint32_t)__cvta_generic_to_shared(p);
}

// Blackwell packed fp32x2 FMA (PTX-only)
#define FMA_F32X2(d, a, b, c) \
    asm("fma.rn.f32x2 %0, %1, %2, %3;" : "=l"(d) : "l"(a), "l"(b), "l"(c))

// ---------------------------------------------------------------------------
// Kernel A: build the 16x16 channel table once (one warp per entry).
// ---------------------------------------------------------------------------
__global__ void __launch_bounds__(1024, 1)
cb_table_kernel(const float* __restrict__ emb,   // [256, D]
                const float* __restrict__ W,     // [16, D]
                const float* __restrict__ bias)  // [16]
{
    const int w = (blockIdx.x * blockDim.x + threadIdx.x) >> 5;  // 0..255
    const int l = threadIdx.x & 31;
    const int c = w >> 4, p = w & 15;

    float4 e = *reinterpret_cast<const float4*>(emb + (size_t)c * D_ + l * 4);
    float4 v = *reinterpret_cast<const float4*>(W   + (size_t)p * D_ + l * 4);
    float s = e.x * v.x + e.y * v.y + e.z * v.z + e.w * v.w;
    #pragma unroll
    for (int off = 16; off > 0; off >>= 1)
        s += __shfl_xor_sync(0xffffffffu, s, off);
    if (l == 0) g_cb[w] = s + bias[p];
}

// ---------------------------------------------------------------------------
// Kernel B: main fused decode. 4 threads per token row (adjacent lanes ->
// broadcast LDS), 4 packed accumulators each.
// ---------------------------------------------------------------------------
__global__ void __launch_bounds__(THREADS, 4)
QBD_main_kernel(
    const float* __restrict__ x,     // [B, N, D]
    const float* __restrict__ pmask, // [B, C]
    const float* __restrict__ W,     // [16, D]
    float* __restrict__ out)         // [B, C, 128, 128]
{
    extern __shared__ float sm[];
    float* sx    = sm + SX_OFF;
    float* sw    = sm + SW_OFF;
    float* scbm  = sm + SCBM_OFF;
    float* smask = sm + SMASK_OFF;

    const int b  = blockIdx.y;
    const int n0 = blockIdx.x * NT;
    const int t  = threadIdx.x;

    // ---- Stage x tile (64x128 floats = 32KB contiguous) via cp.async,
    //      XOR-swizzled: phys 16B-chunk col = c ^ (row & 7) ----
    const float4* gx = reinterpret_cast<const float4*>(x + ((size_t)b * N_ + n0) * D_);
    #pragma unroll
    for (int i = 0; i < 8; ++i) {
        int k = t + THREADS * i;                 // 0..2047: row = k>>5, c = k&31
        int row = k >> 5, c = k & 31;
        uint32_t dst = smem_u32(sx + row * D_ + ((c ^ (row & 7)) << 2));
        asm volatile("cp.async.cg.shared.global [%0], [%1], 16;\n"
                     :: "r"(dst), "l"(gx + k));
    }
    // ---- Stage W (16x128 floats), same swizzle keyed by W row & 7 ----
    const float4* gw = reinterpret_cast<const float4*>(W);
    #pragma unroll
    for (int i = 0; i < 2; ++i) {
        int k = t + THREADS * i;                 // 0..511
        int wrow = k >> 5, c = k & 31;
        uint32_t dst = smem_u32(sw + wrow * D_ + ((c ^ (wrow & 7)) << 2));
        asm volatile("cp.async.cg.shared.global [%0], [%1], 16;\n"
                     :: "r"(dst), "l"(gw + k));
    }
    asm volatile("cp.async.commit_group;\n");

    // ---- Load precomputed channel table (1KB, L2-hot) + masks, overlapped ----
    {
        float m = pmask[b * C_ + (t >> 4)];
        scbm[t] = g_cb[t] * m;
        if (t < C_) smask[t] = pmask[b * C_ + t];
    }

    asm volatile("cp.async.wait_group 0;\n");
    __syncthreads();

    // ---- Main dot products. Thread (row, q) computes xa[row][q*4 + jj], jj=0..3.
    //      xv: 4 lanes/row share the address -> smem broadcast; 8 rows/warp have
    //      distinct swizzle keys covering all 32 banks -> conflict-free. ----
    const int row = t >> 2;                      // 0..63
    const int q   = t & 3;                       // patch row
    const float* xr = sx + row * D_;
    const int    xs = row & 7;

    unsigned long long acc2[4] = {0ull, 0ull, 0ull, 0ull};

    #pragma unroll
    for (int d4 = 0; d4 < 32; ++d4) {
        ulonglong2 xv = *reinterpret_cast<const ulonglong2*>(xr + ((d4 ^ xs) << 2));
        #pragma unroll
        for (int jj = 0; jj < 4; ++jj) {
            const int j = q * 4 + jj;
            const ulonglong2 wv = *reinterpret_cast<const ulonglong2*>(
                sw + j * D_ + ((d4 ^ (j & 7)) << 2));   // warp-uniform per q -> broadcast
            FMA_F32X2(acc2[jj], xv.x, wv.x, acc2[jj]);
            FMA_F32X2(acc2[jj], xv.y, wv.y, acc2[jj]);
        }
    }

    // ---- Horizontal add (even+odd), re-pack for packed epilogue ----
    float xa[4];
    #pragma unroll
    for (int jj = 0; jj < 4; ++jj) {
        uint32_t lo, hi;
        asm("mov.b64 {%0, %1}, %2;" : "=r"(lo), "=r"(hi) : "l"(acc2[jj]));
        xa[jj] = __uint_as_float(lo) + __uint_as_float(hi);
    }
    unsigned long long xa2[2];
    #pragma unroll
    for (int k = 0; k < 2; ++k)
        asm("mov.b64 %0, {%1, %2};" : "=l"(xa2[k])
            : "r"(__float_as_uint(xa[2 * k])), "r"(__float_as_uint(xa[2 * k + 1])));

    // ---- Epilogue: out[b][c][hg*4+q][wg*4 + jj] = xa[jj]*m_c + cbm[c][q*4+jj]
    //      One STG.128 per channel; 8 same-q lanes form a contiguous 128B line. ----
    const int n  = n0 + row;
    const int hg = n >> 5, wg = n & 31;
    float* ob = out + (size_t)b * (C_ * 128 * 128) + (hg * 4 + q) * 128 + wg * 4;

    #pragma unroll
    for (int c = 0; c < C_; ++c) {
        float m = smask[c];
        unsigned long long m2;
        asm("mov.b64 %0, {%1, %1};" : "=l"(m2) : "r"(__float_as_uint(m)));
        ulonglong2 cb = *reinterpret_cast<const ulonglong2*>(scbm + c * 16 + q * 4);
        ulonglong2 v;
        FMA_F32X2(v.x, xa2[0], m2, cb.x);
        FMA_F32X2(v.y, xa2[1], m2, cb.y);
        *reinterpret_cast<ulonglong2*>(ob + c * (128 * 128)) = v;
    }
}

extern "C" void kernel_launch(void* const* d_in, const int* in_sizes, int n_in,
                              void* d_out, int out_size)
{
    const float* x    = (const float*)d_in[0];  // [32,1024,128]
    const float* pm   = (const float*)d_in[1];  // [32,16]
    const float* emb  = (const float*)d_in[2];  // [256,128]
    const float* W    = (const float*)d_in[3];  // [16,128]
    const float* bias = (const float*)d_in[4];  // [16]
    float* out        = (float*)d_out;          // [32,16,128,128]

    // Kernel A: 256-entry channel table (one warp per entry)
    cb_table_kernel<<<8, 1024>>>(emb, W, bias);

    // Kernel B: main fused decode — 512 CTAs, all resident in a single wave
    cudaFuncSetAttribute(QBD_main_kernel,
                         cudaFuncAttributeMaxDynamicSharedMemorySize, SMEM_BYTES);
    dim3 grid(N_ / NT, B_);   // (16, 32) = 512 blocks
    QBD_main_kernel<<<grid, THREADS, SMEM_BYTES>>>(x, pm, W, out);
}

// round 6
// speedup vs baseline: 1.7665x; 1.7665x over previous
#include <cuda_runtime.h>
#include <cstdint>
#include <cstddef>

// Problem constants (fixed by the dataset)
#define B_  32
#define N_  1024
#define D_  128
#define C_  16
// P*P = 16, Hg = 32, out image 128x128 per (b,c)

// Tiling: thread t -> (row = t & 63, q = t >> 6). Each warp: 32 consecutive
// rows, ONE q -> wv loads warp-uniform (broadcast), xv at its 4-phase floor.
#define NT      64
#define THREADS 256

// Shared layout (floats) — x tile XOR-swizzled at 16B-chunk granularity
#define SX_OFF    0                    // [64][128] swizzled, 32KB
#define SW_OFF    (NT * D_)            // 8192: [16][128] swizzled
#define SCBM_OFF  (SW_OFF + 16 * D_)   // 10240: [16][16] mask-premultiplied
#define SMASK_OFF (SCBM_OFF + 256)     // 10496: [16]
#define SMEM_FLOATS (SMASK_OFF + 16)   // 10512
#define SMEM_BYTES  (SMEM_FLOATS * 4)  // 42048 -> 4 CTAs/SM (168KB), 512-CTA grid ~3.5/SM

// Precomputed channel table: cb[c*16+p] = emb[c]·W[p] + bias[p]
__device__ float g_cb[C_ * 16];

__device__ __forceinline__ uint32_t smem_u32(const void* p) {
    return (uint32_t)__cvta_generic_to_shared(p);
}

// Blackwell packed fp32x2 FMA (PTX-only)
#define FMA_F32X2(d, a, b, c) \
    asm("fma.rn.f32x2 %0, %1, %2, %3;" : "=l"(d) : "l"(a), "l"(b), "l"(c))

// ---------------------------------------------------------------------------
// Kernel A: build the 16x16 channel table once (one warp per entry).
// ---------------------------------------------------------------------------
__global__ void __launch_bounds__(1024, 1)
cb_table_kernel(const float* __restrict__ emb,   // [256, D]
                const float* __restrict__ W,     // [16, D]
                const float* __restrict__ bias)  // [16]
{
    const int w = (blockIdx.x * blockDim.x + threadIdx.x) >> 5;  // 0..255
    const int l = threadIdx.x & 31;
    const int c = w >> 4, p = w & 15;

    float4 e = *reinterpret_cast<const float4*>(emb + (size_t)c * D_ + l * 4);
    float4 v = *reinterpret_cast<const float4*>(W   + (size_t)p * D_ + l * 4);
    float s = e.x * v.x + e.y * v.y + e.z * v.z + e.w * v.w;
    #pragma unroll
    for (int off = 16; off > 0; off >>= 1)
        s += __shfl_xor_sync(0xffffffffu, s, off);
    if (l == 0) g_cb[w] = s + bias[p];
}

// ---------------------------------------------------------------------------
// Kernel B: main fused decode.
// ---------------------------------------------------------------------------
__global__ void __launch_bounds__(THREADS, 4)
QBD_main_kernel(
    const float* __restrict__ x,     // [B, N, D]
    const float* __restrict__ pmask, // [B, C]
    const float* __restrict__ W,     // [16, D]
    float* __restrict__ out)         // [B, C, 128, 128]
{
    extern __shared__ float sm[];
    float* sx    = sm + SX_OFF;
    float* sw    = sm + SW_OFF;
    float* scbm  = sm + SCBM_OFF;
    float* smask = sm + SMASK_OFF;

    const int b  = blockIdx.y;
    const int n0 = blockIdx.x * NT;
    const int t  = threadIdx.x;

    // ---- Stage x tile (64x128 floats = 32KB contiguous) via cp.async,
    //      XOR-swizzled: phys 16B-chunk col = c ^ (row & 7) ----
    const float4* gx = reinterpret_cast<const float4*>(x + ((size_t)b * N_ + n0) * D_);
    #pragma unroll
    for (int i = 0; i < 8; ++i) {
        int k = t + THREADS * i;                 // 0..2047: row = k>>5, c = k&31
        int row = k >> 5, c = k & 31;
        uint32_t dst = smem_u32(sx + row * D_ + ((c ^ (row & 7)) << 2));
        asm volatile("cp.async.cg.shared.global [%0], [%1], 16;\n"
                     :: "r"(dst), "l"(gx + k));
    }
    // ---- Stage W (16x128 floats), same swizzle keyed by W row & 7 ----
    const float4* gw = reinterpret_cast<const float4*>(W);
    #pragma unroll
    for (int i = 0; i < 2; ++i) {
        int k = t + THREADS * i;                 // 0..511
        int wrow = k >> 5, c = k & 31;
        uint32_t dst = smem_u32(sw + wrow * D_ + ((c ^ (wrow & 7)) << 2));
        asm volatile("cp.async.cg.shared.global [%0], [%1], 16;\n"
                     :: "r"(dst), "l"(gw + k));
    }
    asm volatile("cp.async.commit_group;\n");

    // ---- Load precomputed channel table (1KB, L2-hot) + masks, overlapped ----
    {
        float m = pmask[b * C_ + (t >> 4)];
        scbm[t] = g_cb[t] * m;
        if (t < C_) smask[t] = pmask[b * C_ + t];
    }

    asm volatile("cp.async.wait_group 0;\n");
    __syncthreads();

    // ---- Main dot products. Thread (row, q) computes xa[row][q*4+jj].
    //      Warp = 32 consecutive rows, one q:
    //        xv: 32 distinct 16B addrs (4-phase floor, conflict-free via swizzle)
    //        wv: warp-uniform address -> broadcast, 1 phase each ----
    const int row = t & 63;
    const int q   = t >> 6;                      // patch row (uniform per warp)
    const float* xr = sx + row * D_;
    const int    xs = row & 7;

    unsigned long long acc2[4] = {0ull, 0ull, 0ull, 0ull};

    #pragma unroll
    for (int d4 = 0; d4 < 32; ++d4) {
        ulonglong2 xv = *reinterpret_cast<const ulonglong2*>(xr + ((d4 ^ xs) << 2));
        #pragma unroll
        for (int jj = 0; jj < 4; ++jj) {
            const int j = q * 4 + jj;            // warp-uniform
            const ulonglong2 wv = *reinterpret_cast<const ulonglong2*>(
                sw + j * D_ + ((d4 ^ (j & 7)) << 2));
            FMA_F32X2(acc2[jj], xv.x, wv.x, acc2[jj]);
            FMA_F32X2(acc2[jj], xv.y, wv.y, acc2[jj]);
        }
    }

    // ---- Horizontal add (even+odd), re-pack for packed epilogue ----
    float xa[4];
    #pragma unroll
    for (int jj = 0; jj < 4; ++jj) {
        uint32_t lo, hi;
        asm("mov.b64 {%0, %1}, %2;" : "=r"(lo), "=r"(hi) : "l"(acc2[jj]));
        xa[jj] = __uint_as_float(lo) + __uint_as_float(hi);
    }
    unsigned long long xa2[2];
    #pragma unroll
    for (int k = 0; k < 2; ++k)
        asm("mov.b64 %0, {%1, %2};" : "=l"(xa2[k])
            : "r"(__float_as_uint(xa[2 * k])), "r"(__float_as_uint(xa[2 * k + 1])));

    // ---- Epilogue: out[b][c][hg*4+q][wg*4+jj] = xa[jj]*m_c + cbm[c][q*4+jj]
    //      Warp = 32 consecutive n, same hg & q -> one contiguous 512B line
    //      per (warp, c) STG.128 ----
    const int n  = n0 + row;
    const int hg = n >> 5, wg = n & 31;
    float* ob = out + (size_t)b * (C_ * 128 * 128) + (hg * 4 + q) * 128 + wg * 4;

    #pragma unroll
    for (int c = 0; c < C_; ++c) {
        float m = smask[c];
        unsigned long long m2;
        asm("mov.b64 %0, {%1, %1};" : "=l"(m2) : "r"(__float_as_uint(m)));
        ulonglong2 cb = *reinterpret_cast<const ulonglong2*>(scbm + c * 16 + q * 4);
        ulonglong2 v;
        FMA_F32X2(v.x, xa2[0], m2, cb.x);
        FMA_F32X2(v.y, xa2[1], m2, cb.y);
        *reinterpret_cast<ulonglong2*>(ob + c * (128 * 128)) = v;
    }
}

extern "C" void kernel_launch(void* const* d_in, const int* in_sizes, int n_in,
                              void* d_out, int out_size)
{
    const float* x    = (const float*)d_in[0];  // [32,1024,128]
    const float* pm   = (const float*)d_in[1];  // [32,16]
    const float* emb  = (const float*)d_in[2];  // [256,128]
    const float* W    = (const float*)d_in[3];  // [16,128]
    const float* bias = (const float*)d_in[4];  // [16]
    float* out        = (float*)d_out;          // [32,16,128,128]

    // Kernel A: 256-entry channel table (one warp per entry)
    cb_table_kernel<<<8, 1024>>>(emb, W, bias);

    // Kernel B: main fused decode — 512 CTAs, ~3.5/SM, 28 warps/SM
    cudaFuncSetAttribute(QBD_main_kernel,
                         cudaFuncAttributeMaxDynamicSharedMemorySize, SMEM_BYTES);
    dim3 grid(N_ / NT, B_);   // (16, 32) = 512 blocks
    QBD_main_kernel<<<grid, THREADS, SMEM_BYTES>>>(x, pm, W, out);
}